// round 14
// baseline (speedup 1.0000x reference)
#include <cuda_runtime.h>
#include <cuda_bf16.h>
#include <cstdint>
#include <cstddef>

#define BB 4
#define SS 2048
#define DD 1024
#define HH 8
#define HD 128
#define FF 4096
#define ROWS (BB * SS)
#define SCALE 0.08838834764831843f
#define EPS 1e-5f

// ---------------- scratch ----------------
__device__ float g_qkv [(size_t)ROWS * 3 * DD];
__device__ float g_attn[(size_t)ROWS * DD];
__device__ float g_x1  [(size_t)ROWS * DD];
__device__ float g_ffo [(size_t)ROWS * DD];

__device__ __nv_bfloat16 g_xs_h [(size_t)ROWS * DD];
__device__ __nv_bfloat16 g_xs_l [(size_t)ROWS * DD];
__device__ __nv_bfloat16 g_wqkv_h[(size_t)3 * DD * DD];
__device__ __nv_bfloat16 g_wqkv_l[(size_t)3 * DD * DD];
__device__ __nv_bfloat16 g_wo_h [(size_t)DD * DD];
__device__ __nv_bfloat16 g_wo_l [(size_t)DD * DD];
__device__ __nv_bfloat16 g_w1_h [(size_t)FF * DD];
__device__ __nv_bfloat16 g_w1_l [(size_t)FF * DD];
__device__ __nv_bfloat16 g_w2_h [(size_t)DD * FF];
__device__ __nv_bfloat16 g_w2_l [(size_t)DD * FF];
__device__ __nv_bfloat16 g_qh [(size_t)BB * HH * SS * HD];
__device__ __nv_bfloat16 g_ql [(size_t)BB * HH * SS * HD];
__device__ __nv_bfloat16 g_kh [(size_t)BB * HH * SS * HD];
__device__ __nv_bfloat16 g_vth[(size_t)BB * HH * HD * SS];
__device__ __nv_bfloat16 g_vls_h[(size_t)ROWS * DD];
__device__ __nv_bfloat16 g_x1s_h[(size_t)ROWS * DD];
__device__ __nv_bfloat16 g_x1s_l[(size_t)ROWS * DD];
__device__ __nv_bfloat16 g_ffh_h[(size_t)ROWS * FF];
__device__ __nv_bfloat16 g_ffh_l[(size_t)ROWS * FF];

// ======================= helpers ===================
__device__ __forceinline__ uint32_t smem_u32(const void* p) {
    uint32_t a;
    asm("{ .reg .u64 t; cvta.to.shared.u64 t, %1; cvt.u32.u64 %0, t; }"
        : "=r"(a) : "l"(p));
    return a;
}
__device__ __forceinline__ void mma_bf16(float* d,
    uint32_t a0, uint32_t a1, uint32_t a2, uint32_t a3, uint32_t b0, uint32_t b1)
{
    asm volatile(
        "mma.sync.aligned.m16n8k16.row.col.f32.bf16.bf16.f32 "
        "{%0,%1,%2,%3}, {%4,%5,%6,%7}, {%8,%9}, {%0,%1,%2,%3};"
        : "+f"(d[0]), "+f"(d[1]), "+f"(d[2]), "+f"(d[3])
        : "r"(a0), "r"(a1), "r"(a2), "r"(a3), "r"(b0), "r"(b1));
}
__device__ __forceinline__ void cp16(uint32_t dst, const void* src) {
    asm volatile("cp.async.cg.shared.global [%0], [%1], 16;" :: "r"(dst), "l"(src));
}
#define CP_COMMIT() asm volatile("cp.async.commit_group;" ::: "memory")
#define CP_WAIT1()  asm volatile("cp.async.wait_group 1;" ::: "memory")
#define CP_WAIT0()  asm volatile("cp.async.wait_group 0;" ::: "memory")

__device__ __forceinline__ uint32_t packbf(float x, float y) {
    __nv_bfloat162 t(__float2bfloat16(x), __float2bfloat16(y));
    return *reinterpret_cast<uint32_t*>(&t);
}

// =================== bf16x3/x2 tensor-core GEMM: C = A @ B^T ==================
// alo=1: full bf16x3 (Ahi*Bhi + Ahi*Blo + Alo*Bhi). alo=0: drop Alo term and
// skip loading the Alo tile entirely (bf16x2).
#define RS 80
#define TB (128 * RS)
#define STAGE_BYTES (4 * TB)
#define SM_MMA_TOTAL (2 * STAGE_BYTES)

__global__ void __launch_bounds__(256, 2) tgemm(
    const __nv_bfloat16* __restrict__ Ahi, const __nv_bfloat16* __restrict__ Alo,
    const __nv_bfloat16* __restrict__ Bhi, const __nv_bfloat16* __restrict__ Blo,
    float* __restrict__ C, __nv_bfloat16* __restrict__ Chi,
    __nv_bfloat16* __restrict__ Clo,
    int Kdim, int lda, int ldb, int ldc, int relu, int alo)
{
    extern __shared__ char smem[];
    uint32_t sb = smem_u32(smem);

    int tid = threadIdx.x;
    int wid = tid >> 5, lane = tid & 31;
    int gid = lane >> 2, tig = lane & 3;
    int warp_m = wid >> 1;
    int warp_n = wid & 1;
    int rowC0 = blockIdx.y * 128;
    int colC0 = blockIdx.x * 128;

    int lr   = tid >> 1;
    int seg2 = (tid & 1) * 2;

    float acc[2][8][4] = {};
    int nstages = Kdim >> 5;

    {
        const char* gAh = (const char*)(Ahi + (size_t)(rowC0 + lr) * lda) + seg2 * 16;
        const char* gBh = (const char*)(Bhi + (size_t)(colC0 + lr) * ldb) + seg2 * 16;
        const char* gBl = (const char*)(Blo + (size_t)(colC0 + lr) * ldb) + seg2 * 16;
        uint32_t s = sb + lr * RS + seg2 * 16;
        cp16(s,          gAh); cp16(s + 16,          gAh + 16);
        cp16(s + 2 * TB, gBh); cp16(s + 2 * TB + 16, gBh + 16);
        cp16(s + 3 * TB, gBl); cp16(s + 3 * TB + 16, gBl + 16);
        if (alo) {
            const char* gAl = (const char*)(Alo + (size_t)(rowC0 + lr) * lda) + seg2 * 16;
            cp16(s + TB, gAl); cp16(s + TB + 16, gAl + 16);
        }
        CP_COMMIT();
    }

    for (int st = 0; st < nstages; st++) {
        if (st + 1 < nstages) {
            int k0 = (st + 1) << 5;
            uint32_t base = sb + ((st + 1) & 1) * STAGE_BYTES;
            const char* gAh = (const char*)(Ahi + (size_t)(rowC0 + lr) * lda + k0) + seg2 * 16;
            const char* gBh = (const char*)(Bhi + (size_t)(colC0 + lr) * ldb + k0) + seg2 * 16;
            const char* gBl = (const char*)(Blo + (size_t)(colC0 + lr) * ldb + k0) + seg2 * 16;
            uint32_t s = base + lr * RS + seg2 * 16;
            cp16(s,          gAh); cp16(s + 16,          gAh + 16);
            cp16(s + 2 * TB, gBh); cp16(s + 2 * TB + 16, gBh + 16);
            cp16(s + 3 * TB, gBl); cp16(s + 3 * TB + 16, gBl + 16);
            if (alo) {
                const char* gAl = (const char*)(Alo + (size_t)(rowC0 + lr) * lda + k0) + seg2 * 16;
                cp16(s + TB, gAl); cp16(s + TB + 16, gAl + 16);
            }
            CP_COMMIT();
            CP_WAIT1();
        } else {
            CP_WAIT0();
        }
        __syncthreads();

        const char* buf = smem + (st & 1) * STAGE_BYTES;
#pragma unroll
        for (int ks = 0; ks < 2; ks++) {
            int kbyte = ks * 32 + tig * 4;
            uint32_t ah[2][4], al[2][4];
#pragma unroll
            for (int mi = 0; mi < 2; mi++) {
                const char* ra = buf + (warp_m * 32 + mi * 16 + gid) * RS + kbyte;
                ah[mi][0] = *(const uint32_t*)(ra);
                ah[mi][1] = *(const uint32_t*)(ra + 8 * RS);
                ah[mi][2] = *(const uint32_t*)(ra + 16);
                ah[mi][3] = *(const uint32_t*)(ra + 8 * RS + 16);
                if (alo) {
                    al[mi][0] = *(const uint32_t*)(ra + TB);
                    al[mi][1] = *(const uint32_t*)(ra + TB + 8 * RS);
                    al[mi][2] = *(const uint32_t*)(ra + TB + 16);
                    al[mi][3] = *(const uint32_t*)(ra + TB + 8 * RS + 16);
                }
            }
#pragma unroll
            for (int ni = 0; ni < 8; ni++) {
                const char* rb = buf + 2 * TB + (warp_n * 64 + ni * 8 + gid) * RS + kbyte;
                uint32_t bh0 = *(const uint32_t*)(rb);
                uint32_t bh1 = *(const uint32_t*)(rb + 16);
                uint32_t bl0 = *(const uint32_t*)(rb + TB);
                uint32_t bl1 = *(const uint32_t*)(rb + TB + 16);
#pragma unroll
                for (int mi = 0; mi < 2; mi++) {
                    mma_bf16(acc[mi][ni], ah[mi][0], ah[mi][1], ah[mi][2], ah[mi][3], bh0, bh1);
                    mma_bf16(acc[mi][ni], ah[mi][0], ah[mi][1], ah[mi][2], ah[mi][3], bl0, bl1);
                    if (alo)
                        mma_bf16(acc[mi][ni], al[mi][0], al[mi][1], al[mi][2], al[mi][3], bh0, bh1);
                }
            }
        }
        __syncthreads();
    }

#pragma unroll
    for (int mi = 0; mi < 2; mi++) {
        int row0 = rowC0 + warp_m * 32 + mi * 16 + gid;
        int colB = colC0 + warp_n * 64 + tig * 2;
#pragma unroll
        for (int half = 0; half < 2; half++) {
            int row = row0 + half * 8;
#pragma unroll
            for (int ni = 0; ni < 8; ni++) {
                float v0 = acc[mi][ni][half * 2 + 0];
                float v1 = acc[mi][ni][half * 2 + 1];
                if (relu) { v0 = fmaxf(v0, 0.f); v1 = fmaxf(v1, 0.f); }
                if (Chi) {
                    __nv_bfloat16 h0 = __float2bfloat16(v0);
                    __nv_bfloat16 h1 = __float2bfloat16(v1);
                    __nv_bfloat162 hv(h0, h1);
                    __nv_bfloat162 lv(__float2bfloat16(v0 - __bfloat162float(h0)),
                                      __float2bfloat16(v1 - __bfloat162float(h1)));
                    *(__nv_bfloat162*)(Chi + (size_t)row * ldc + colB + ni * 8) = hv;
                    *(__nv_bfloat162*)(Clo + (size_t)row * ldc + colB + ni * 8) = lv;
                } else {
                    *(float2*)(C + (size_t)row * ldc + colB + ni * 8) = make_float2(v0, v1);
                }
            }
        }
    }
}

// ======================= flash attention ======================================
// S = (Qhi+Qlo)*Khi, O = (Phi+Plo)*Vhi. Output: vals hi only (Wo gemm is bf16x2).
#define FTK 64
#define RSQ 272
#define RSV 144
#define SZ_Q (128 * RSQ)
#define SZ_K (64 * RSQ)
#define SZ_V (128 * RSV)
#define OFF_QH 0
#define OFF_QL SZ_Q
#define OFF_BUF (2 * SZ_Q)
#define BUF_SZ (SZ_K + SZ_V)
#define B_KH 0
#define B_VH SZ_K
#define SM_FLASH (OFF_BUF + 2 * BUF_SZ)  // 141312

__global__ void __launch_bounds__(256) fattn(
    const __nv_bfloat16* __restrict__ Qh, const __nv_bfloat16* __restrict__ Ql,
    const __nv_bfloat16* __restrict__ Kh,
    const __nv_bfloat16* __restrict__ VTh,
    __nv_bfloat16* __restrict__ Oh)
{
    extern __shared__ char smem[];
    uint32_t sb = smem_u32(smem);

    int tid = threadIdx.x;
    int wid = tid >> 5, lane = tid & 31;
    int gid = lane >> 2, tig = lane & 3;
    int q0 = blockIdx.x * 128;
    int bh = blockIdx.y;
    int b = bh >> 3, h = bh & 7;

    const __nv_bfloat16* qh_g = Qh + (size_t)bh * SS * HD;
    const __nv_bfloat16* ql_g = Ql + (size_t)bh * SS * HD;
    const __nv_bfloat16* kh_g = Kh + (size_t)bh * SS * HD;
    const __nv_bfloat16* vh_g = VTh + (size_t)bh * HD * SS;

    for (int i = tid; i < 128 * 16; i += 256) {
        int r = i >> 4, sg = i & 15;
        cp16(sb + OFF_QH + r * RSQ + sg * 16, qh_g + (size_t)(q0 + r) * HD + sg * 8);
        cp16(sb + OFF_QL + r * RSQ + sg * 16, ql_g + (size_t)(q0 + r) * HD + sg * 8);
    }
    {
        uint32_t bbuf = sb + OFF_BUF;
        for (int i = tid; i < 64 * 16; i += 256) {
            int r = i >> 4, sg = i & 15;
            cp16(bbuf + B_KH + r * RSQ + sg * 16, kh_g + (size_t)r * HD + sg * 8);
        }
        for (int i = tid; i < 128 * 8; i += 256) {
            int r = i >> 3, sg = i & 7;
            cp16(bbuf + B_VH + r * RSV + sg * 16, vh_g + (size_t)r * SS + sg * 8);
        }
    }
    CP_COMMIT();

    float oacc[16][4] = {};
    float m0 = -1e30f, m1 = -1e30f, l0 = 0.f, l1 = 0.f;

    const int NIT = SS / FTK;
    for (int it = 0; it < NIT; it++) {
        if (it + 1 < NIT) {
            int kv0 = (it + 1) * FTK;
            uint32_t bbuf = sb + OFF_BUF + ((it + 1) & 1) * BUF_SZ;
            for (int i = tid; i < 64 * 16; i += 256) {
                int r = i >> 4, sg = i & 15;
                cp16(bbuf + B_KH + r * RSQ + sg * 16, kh_g + (size_t)(kv0 + r) * HD + sg * 8);
            }
            for (int i = tid; i < 128 * 8; i += 256) {
                int r = i >> 3, sg = i & 7;
                cp16(bbuf + B_VH + r * RSV + sg * 16, vh_g + (size_t)r * SS + kv0 + sg * 8);
            }
            CP_COMMIT();
            CP_WAIT1();
        } else {
            CP_WAIT0();
        }
        __syncthreads();

        const char* buf = smem + OFF_BUF + (it & 1) * BUF_SZ;
        const char* qbh = smem + OFF_QH;
        const char* qbl = smem + OFF_QL;

        float s[8][4] = {};
#pragma unroll
        for (int kc = 0; kc < 8; kc++) {
            int kbyte = kc * 32 + tig * 4;
            const char* ra = qbh + (wid * 16 + gid) * RSQ + kbyte;
            const char* rl = qbl + (wid * 16 + gid) * RSQ + kbyte;
            uint32_t ah0 = *(const uint32_t*)(ra);
            uint32_t ah1 = *(const uint32_t*)(ra + 8 * RSQ);
            uint32_t ah2 = *(const uint32_t*)(ra + 16);
            uint32_t ah3 = *(const uint32_t*)(ra + 8 * RSQ + 16);
            uint32_t al0 = *(const uint32_t*)(rl);
            uint32_t al1 = *(const uint32_t*)(rl + 8 * RSQ);
            uint32_t al2 = *(const uint32_t*)(rl + 16);
            uint32_t al3 = *(const uint32_t*)(rl + 8 * RSQ + 16);
#pragma unroll
            for (int nt = 0; nt < 8; nt++) {
                const char* rb = buf + B_KH + (nt * 8 + gid) * RSQ + kbyte;
                uint32_t bh0 = *(const uint32_t*)(rb);
                uint32_t bh1 = *(const uint32_t*)(rb + 16);
                mma_bf16(s[nt], ah0, ah1, ah2, ah3, bh0, bh1);
                mma_bf16(s[nt], al0, al1, al2, al3, bh0, bh1);
            }
        }

        float ms0 = -1e30f, ms1 = -1e30f;
#pragma unroll
        for (int nt = 0; nt < 8; nt++) {
            ms0 = fmaxf(ms0, fmaxf(s[nt][0], s[nt][1]));
            ms1 = fmaxf(ms1, fmaxf(s[nt][2], s[nt][3]));
        }
        ms0 = fmaxf(ms0, __shfl_xor_sync(0xffffffffu, ms0, 1));
        ms0 = fmaxf(ms0, __shfl_xor_sync(0xffffffffu, ms0, 2));
        ms1 = fmaxf(ms1, __shfl_xor_sync(0xffffffffu, ms1, 1));
        ms1 = fmaxf(ms1, __shfl_xor_sync(0xffffffffu, ms1, 2));
        float mn0 = fmaxf(m0, ms0 * SCALE);
        float mn1 = fmaxf(m1, ms1 * SCALE);
        float a0 = __expf(m0 - mn0);
        float a1 = __expf(m1 - mn1);
        float r0 = 0.f, r1 = 0.f;
#pragma unroll
        for (int nt = 0; nt < 8; nt++) {
            s[nt][0] = __expf(fmaf(s[nt][0], SCALE, -mn0));
            s[nt][1] = __expf(fmaf(s[nt][1], SCALE, -mn0));
            s[nt][2] = __expf(fmaf(s[nt][2], SCALE, -mn1));
            s[nt][3] = __expf(fmaf(s[nt][3], SCALE, -mn1));
            r0 += s[nt][0] + s[nt][1];
            r1 += s[nt][2] + s[nt][3];
        }
        r0 += __shfl_xor_sync(0xffffffffu, r0, 1);
        r0 += __shfl_xor_sync(0xffffffffu, r0, 2);
        r1 += __shfl_xor_sync(0xffffffffu, r1, 1);
        r1 += __shfl_xor_sync(0xffffffffu, r1, 2);
        l0 = l0 * a0 + r0;
        l1 = l1 * a1 + r1;
        m0 = mn0; m1 = mn1;
#pragma unroll
        for (int nd = 0; nd < 16; nd++) {
            oacc[nd][0] *= a0; oacc[nd][1] *= a0;
            oacc[nd][2] *= a1; oacc[nd][3] *= a1;
        }

#pragma unroll
        for (int t = 0; t < 4; t++) {
            float p00 = s[2 * t][0],     p01 = s[2 * t][1];
            float p10 = s[2 * t][2],     p11 = s[2 * t][3];
            float p20 = s[2 * t + 1][0], p21 = s[2 * t + 1][1];
            float p30 = s[2 * t + 1][2], p31 = s[2 * t + 1][3];
            uint32_t ph0 = packbf(p00, p01);
            uint32_t ph1 = packbf(p10, p11);
            uint32_t ph2 = packbf(p20, p21);
            uint32_t ph3 = packbf(p30, p31);
            __nv_bfloat162 h0 = *reinterpret_cast<__nv_bfloat162*>(&ph0);
            __nv_bfloat162 h1 = *reinterpret_cast<__nv_bfloat162*>(&ph1);
            __nv_bfloat162 h2 = *reinterpret_cast<__nv_bfloat162*>(&ph2);
            __nv_bfloat162 h3 = *reinterpret_cast<__nv_bfloat162*>(&ph3);
            uint32_t pl0 = packbf(p00 - __bfloat162float(h0.x), p01 - __bfloat162float(h0.y));
            uint32_t pl1 = packbf(p10 - __bfloat162float(h1.x), p11 - __bfloat162float(h1.y));
            uint32_t pl2 = packbf(p20 - __bfloat162float(h2.x), p21 - __bfloat162float(h2.y));
            uint32_t pl3 = packbf(p30 - __bfloat162float(h3.x), p31 - __bfloat162float(h3.y));
            int kbyte = t * 32 + tig * 4;
#pragma unroll
            for (int nd = 0; nd < 16; nd++) {
                const char* rb = buf + B_VH + (nd * 8 + gid) * RSV + kbyte;
                uint32_t vh0 = *(const uint32_t*)(rb);
                uint32_t vh1 = *(const uint32_t*)(rb + 16);
                mma_bf16(oacc[nd], ph0, ph1, ph2, ph3, vh0, vh1);
                mma_bf16(oacc[nd], pl0, pl1, pl2, pl3, vh0, vh1);
            }
        }
        __syncthreads();
    }

    float inv0 = 1.0f / l0, inv1 = 1.0f / l1;
    int row0 = b * SS + q0 + wid * 16 + gid;
    int colB = h * HD + tig * 2;
#pragma unroll
    for (int nd = 0; nd < 16; nd++) {
#pragma unroll
        for (int half = 0; half < 2; half++) {
            float v0 = oacc[nd][half * 2 + 0] * (half ? inv1 : inv0);
            float v1 = oacc[nd][half * 2 + 1] * (half ? inv1 : inv0);
            __nv_bfloat162 hv(__float2bfloat16(v0), __float2bfloat16(v1));
            size_t addr = (size_t)(row0 + half * 8) * DD + colB + nd * 8;
            *(__nv_bfloat162*)(Oh + addr) = hv;
        }
    }
}

// ---------------- split fp32 -> hi/lo bf16, flat ------------------------------
__global__ void __launch_bounds__(256) split_flat(
    const float* __restrict__ in, __nv_bfloat16* __restrict__ hi,
    __nv_bfloat16* __restrict__ lo, long long n4)
{
    long long i = (long long)blockIdx.x * 256 + threadIdx.x;
    if (i >= n4) return;
    float4 v = ((const float4*)in)[i];
    __nv_bfloat16 h0 = __float2bfloat16(v.x), h1 = __float2bfloat16(v.y);
    __nv_bfloat16 h2 = __float2bfloat16(v.z), h3 = __float2bfloat16(v.w);
    __nv_bfloat162* H = (__nv_bfloat162*)hi;
    __nv_bfloat162* L = (__nv_bfloat162*)lo;
    H[2 * i]     = __nv_bfloat162(h0, h1);
    H[2 * i + 1] = __nv_bfloat162(h2, h3);
    L[2 * i]     = __nv_bfloat162(__float2bfloat16(v.x - __bfloat162float(h0)),
                                  __float2bfloat16(v.y - __bfloat162float(h1)));
    L[2 * i + 1] = __nv_bfloat162(__float2bfloat16(v.z - __bfloat162float(h2)),
                                  __float2bfloat16(v.w - __bfloat162float(h3)));
}

// --------- fused weight splits ------------------------------------------------
__global__ void __launch_bounds__(256) split_weights(
    const float* __restrict__ Wqkv, const float* __restrict__ Wo,
    const float* __restrict__ W1,   const float* __restrict__ W2,
    __nv_bfloat16* __restrict__ qkv_h, __nv_bfloat16* __restrict__ qkv_l,
    __nv_bfloat16* __restrict__ wo_h,  __nv_bfloat16* __restrict__ wo_l,
    __nv_bfloat16* __restrict__ w1_h,  __nv_bfloat16* __restrict__ w1_l,
    __nv_bfloat16* __restrict__ w2_h,  __nv_bfloat16* __restrict__ w2_l)
{
    int bid = blockIdx.x;
    const float* W; __nv_bfloat16 *hi, *lo; int K, N, nbx, local;
    if (bid < 3072)      { W = Wqkv; hi = qkv_h; lo = qkv_l; K = DD; N = 3 * DD; nbx = 96;  local = bid; }
    else if (bid < 4096) { W = Wo;   hi = wo_h;  lo = wo_l;  K = DD; N = DD;     nbx = 32;  local = bid - 3072; }
    else if (bid < 8192) { W = W1;   hi = w1_h;  lo = w1_l;  K = DD; N = FF;     nbx = 128; local = bid - 4096; }
    else                 { W = W2;   hi = w2_h;  lo = w2_l;  K = FF; N = DD;     nbx = 32;  local = bid - 8192; }
    int n0 = (local % nbx) * 32, k0 = (local / nbx) * 32;

    __shared__ float t[32][33];
    int tx = threadIdx.x & 31, ty = threadIdx.x >> 5;
#pragma unroll
    for (int dy = 0; dy < 32; dy += 8)
        t[ty + dy][tx] = W[(size_t)(k0 + ty + dy) * N + n0 + tx];
    __syncthreads();
#pragma unroll
    for (int dy = 0; dy < 32; dy += 8) {
        int n = n0 + ty + dy, k = k0 + tx;
        float v = t[tx][ty + dy];
        __nv_bfloat16 h = __float2bfloat16(v);
        hi[(size_t)n * K + k] = h;
        lo[(size_t)n * K + k] = __float2bfloat16(v - __bfloat162float(h));
    }
}

// ------------- split qkv -> Q(hi/lo), K(hi) arrays [bh][s][hd] ----------------
__global__ void __launch_bounds__(256) split_qk(
    const float* __restrict__ qkv,
    __nv_bfloat16* __restrict__ Qh, __nv_bfloat16* __restrict__ Ql,
    __nv_bfloat16* __restrict__ Kh)
{
    int part = blockIdx.y;
    long long i = (long long)blockIdx.x * 256 + threadIdx.x;
    long long r = i >> 5;
    int hd = (int)(i & 31) * 4;
    int bh = (int)(r / SS);
    int s_ = (int)(r % SS);
    int b = bh >> 3, h = bh & 7;
    const float* src = qkv + ((size_t)(b * SS + s_)) * 3072 + h * 384 + part * 128 + hd;
    float4 v = *(const float4*)src;
    __nv_bfloat16 h0 = __float2bfloat16(v.x), h1 = __float2bfloat16(v.y);
    __nv_bfloat16 h2 = __float2bfloat16(v.z), h3 = __float2bfloat16(v.w);
    __nv_bfloat162 hv0(h0, h1), hv1(h2, h3);
    size_t o = ((size_t)bh * SS + s_) * HD + hd;
    if (part == 0) {
        __nv_bfloat162 lv0(__float2bfloat16(v.x - __bfloat162float(h0)),
                           __float2bfloat16(v.y - __bfloat162float(h1)));
        __nv_bfloat162 lv1(__float2bfloat16(v.z - __bfloat162float(h2)),
                           __float2bfloat16(v.w - __bfloat162float(h3)));
        *(__nv_bfloat162*)(Qh + o)     = hv0;
        *(__nv_bfloat162*)(Qh + o + 2) = hv1;
        *(__nv_bfloat162*)(Ql + o)     = lv0;
        *(__nv_bfloat162*)(Ql + o + 2) = lv1;
    } else {
        *(__nv_bfloat162*)(Kh + o)     = hv0;
        *(__nv_bfloat162*)(Kh + o + 2) = hv1;
    }
}

// ------------- split + transpose V -> VT [bh][hd][s] (hi only) ----------------
__global__ void __launch_bounds__(256) splitTv(
    const float* __restrict__ qkv,
    __nv_bfloat16* __restrict__ VTh)
{
    __shared__ float t[32][33];
    int s0 = blockIdx.x * 32, hd0 = blockIdx.y * 32;
    int bh = blockIdx.z;
    int b = bh >> 3, h = bh & 7;
    int tx = threadIdx.x & 31, ty = threadIdx.x >> 5;
#pragma unroll
    for (int dy = 0; dy < 32; dy += 8)
        t[ty + dy][tx] = qkv[((size_t)(b * SS + s0 + ty + dy)) * 3072 + h * 384 + 256 + hd0 + tx];
    __syncthreads();
#pragma unroll
    for (int dy = 0; dy < 32; dy += 8) {
        int hd = hd0 + ty + dy, s_ = s0 + tx;
        float v = t[tx][ty + dy];
        size_t o = ((size_t)bh * HD + hd) * SS + s_;
        VTh[o] = __float2bfloat16(v);
    }
}

// ------------- fused residual add + LayerNorm (+ optional split) --------------
__global__ void __launch_bounds__(256) add_ln(
    const float* __restrict__ X, const float* __restrict__ R, float* __restrict__ O,
    __nv_bfloat16* __restrict__ Ohi, __nv_bfloat16* __restrict__ Olo)
{
    long long row = blockIdx.x;
    const float* x = X + row * DD;
    const float* r = R + row * DD;
    int tid = threadIdx.x;

    __shared__ float rs[256], rss[256];

    float v[4];
    float s = 0.f, ss2 = 0.f;
#pragma unroll
    for (int i = 0; i < 4; i++) {
        float y = x[tid + i * 256] + r[tid + i * 256];
        v[i] = y;
        s += y;
        ss2 += y * y;
    }
    rs[tid] = s; rss[tid] = ss2;
    __syncthreads();
    for (int st = 128; st > 0; st >>= 1) {
        if (tid < st) { rs[tid] += rs[tid + st]; rss[tid] += rss[tid + st]; }
        __syncthreads();
    }
    float mean = rs[0] * (1.0f / DD);
    float var  = rss[0] * (1.0f / DD) - mean * mean;
    float inv  = rsqrtf(var + EPS);
#pragma unroll
    for (int i = 0; i < 4; i++) {
        float y = (v[i] - mean) * inv;
        O[row * DD + tid + i * 256] = y;
        if (Ohi) {
            __nv_bfloat16 hb = __float2bfloat16(y);
            Ohi[row * DD + tid + i * 256] = hb;
            Olo[row * DD + tid + i * 256] = __float2bfloat16(y - __bfloat162float(hb));
        }
    }
}

// ------------------------------- launcher -------------------------------------
extern "C" void kernel_launch(void* const* d_in, const int* in_sizes, int n_in,
                              void* d_out, int out_size)
{
    const float* x    = (const float*)d_in[0];
    const float* Wqkv = (const float*)d_in[1];
    const float* Wo   = (const float*)d_in[2];
    const float* W1   = (const float*)d_in[3];
    const float* W2   = (const float*)d_in[4];
    float* out = (float*)d_out;

    float *qkv, *attn, *x1, *ffo;
    cudaGetSymbolAddress((void**)&qkv,  g_qkv);
    cudaGetSymbolAddress((void**)&attn, g_attn);
    cudaGetSymbolAddress((void**)&x1,   g_x1);
    cudaGetSymbolAddress((void**)&ffo,  g_ffo);

    __nv_bfloat16 *xs_h, *xs_l, *wqkv_h, *wqkv_l, *wo_h, *wo_l, *w1_h, *w1_l,
                  *w2_h, *w2_l, *qh, *ql, *kh, *vth,
                  *vls_h, *x1s_h, *x1s_l, *ffh_h, *ffh_l;
    cudaGetSymbolAddress((void**)&xs_h,   g_xs_h);
    cudaGetSymbolAddress((void**)&xs_l,   g_xs_l);
    cudaGetSymbolAddress((void**)&wqkv_h, g_wqkv_h);
    cudaGetSymbolAddress((void**)&wqkv_l, g_wqkv_l);
    cudaGetSymbolAddress((void**)&wo_h,   g_wo_h);
    cudaGetSymbolAddress((void**)&wo_l,   g_wo_l);
    cudaGetSymbolAddress((void**)&w1_h,   g_w1_h);
    cudaGetSymbolAddress((void**)&w1_l,   g_w1_l);
    cudaGetSymbolAddress((void**)&w2_h,   g_w2_h);
    cudaGetSymbolAddress((void**)&w2_l,   g_w2_l);
    cudaGetSymbolAddress((void**)&qh,     g_qh);
    cudaGetSymbolAddress((void**)&ql,     g_ql);
    cudaGetSymbolAddress((void**)&kh,     g_kh);
    cudaGetSymbolAddress((void**)&vth,    g_vth);
    cudaGetSymbolAddress((void**)&vls_h,  g_vls_h);
    cudaGetSymbolAddress((void**)&x1s_h,  g_x1s_h);
    cudaGetSymbolAddress((void**)&x1s_l,  g_x1s_l);
    cudaGetSymbolAddress((void**)&ffh_h,  g_ffh_h);
    cudaGetSymbolAddress((void**)&ffh_l,  g_ffh_l);

    cudaFuncSetAttribute(tgemm, cudaFuncAttributeMaxDynamicSharedMemorySize, SM_MMA_TOTAL);
    cudaFuncSetAttribute(fattn, cudaFuncAttributeMaxDynamicSharedMemorySize, SM_FLASH);

    split_weights<<<12288, 256>>>(Wqkv, Wo, W1, W2,
        wqkv_h, wqkv_l, wo_h, wo_l, w1_h, w1_l, w2_h, w2_l);
    split_flat<<<(long long)ROWS * DD / 1024, 256>>>(x, xs_h, xs_l, (long long)ROWS * DD / 4);

    // 1) QKV = x @ Wqkv (bf16x2: drop x_lo term)
    tgemm<<<dim3(3 * DD / 128, ROWS / 128), 256, SM_MMA_TOTAL>>>(
        xs_h, xs_l, wqkv_h, wqkv_l, qkv, nullptr, nullptr, DD, DD, DD, 3 * DD, 0, 0);

    // 2) split qkv into attention operands (Q hi/lo, K hi, VT hi)
    split_qk<<<dim3((unsigned)((long long)BB * HH * SS * HD / 4 / 256), 2), 256>>>(
        qkv, qh, ql, kh);
    splitTv<<<dim3(SS / 32, HD / 32, BB * HH), 256>>>(qkv, vth);

    // 3) flash attention -> vals hi
    fattn<<<dim3(SS / 128, BB * HH), 256, SM_FLASH>>>(
        qh, ql, kh, vth, vls_h);

    // 4) attn = vals @ Wo (bf16x2: vals hi only)
    tgemm<<<dim3(DD / 128, ROWS / 128), 256, SM_MMA_TOTAL>>>(
        vls_h, vls_h, wo_h, wo_l, attn, nullptr, nullptr, DD, DD, DD, DD, 0, 0);

    // 5) x1 = LN(x + attn), fused split
    add_ln<<<ROWS, 256>>>(x, attn, x1, x1s_h, x1s_l);

    // 6) ffh = relu(x1 @ W1), hi/lo out (full bf16x3)
    tgemm<<<dim3(FF / 128, ROWS / 128), 256, SM_MMA_TOTAL>>>(
        x1s_h, x1s_l, w1_h, w1_l, nullptr, ffh_h, ffh_l, DD, DD, DD, FF, 1, 1);

    // 7) ffo = ffh @ W2 (full bf16x3)
    tgemm<<<dim3(DD / 128, ROWS / 128), 256, SM_MMA_TOTAL>>>(
        ffh_h, ffh_l, w2_h, w2_l, ffo, nullptr, nullptr, FF, FF, FF, DD, 0, 1);

    // 8) out = LN(x1 + ffo)
    add_ln<<<ROWS, 256>>>(x1, ffo, out, nullptr, nullptr);
}

// round 15
// speedup vs baseline: 1.0939x; 1.0939x over previous
#include <cuda_runtime.h>
#include <cuda_bf16.h>
#include <cstdint>
#include <cstddef>

#define BB 4
#define SS 2048
#define DD 1024
#define HH 8
#define HD 128
#define FF 4096
#define ROWS (BB * SS)
#define SCALE 0.08838834764831843f
#define EPS 1e-5f

// ---------------- scratch ----------------
__device__ float g_qkv [(size_t)ROWS * 3 * DD];
__device__ float g_attn[(size_t)ROWS * DD];
__device__ float g_x1  [(size_t)ROWS * DD];
__device__ float g_ffo [(size_t)ROWS * DD];

__device__ __nv_bfloat16 g_xs_h [(size_t)ROWS * DD];
__device__ __nv_bfloat16 g_xs_l [(size_t)ROWS * DD];
__device__ __nv_bfloat16 g_wqkv_h[(size_t)3 * DD * DD];
__device__ __nv_bfloat16 g_wqkv_l[(size_t)3 * DD * DD];
__device__ __nv_bfloat16 g_wo_h [(size_t)DD * DD];
__device__ __nv_bfloat16 g_wo_l [(size_t)DD * DD];
__device__ __nv_bfloat16 g_w1_h [(size_t)FF * DD];
__device__ __nv_bfloat16 g_w1_l [(size_t)FF * DD];
__device__ __nv_bfloat16 g_w2_h [(size_t)DD * FF];
__device__ __nv_bfloat16 g_w2_l [(size_t)DD * FF];
__device__ __nv_bfloat16 g_qh [(size_t)BB * HH * SS * HD];
__device__ __nv_bfloat16 g_ql [(size_t)BB * HH * SS * HD];
__device__ __nv_bfloat16 g_kh [(size_t)BB * HH * SS * HD];
__device__ __nv_bfloat16 g_vth[(size_t)BB * HH * HD * SS];
__device__ __nv_bfloat16 g_vls_h[(size_t)ROWS * DD];
__device__ __nv_bfloat16 g_x1s_h[(size_t)ROWS * DD];
__device__ __nv_bfloat16 g_x1s_l[(size_t)ROWS * DD];
__device__ __nv_bfloat16 g_ffh_h[(size_t)ROWS * FF];
__device__ __nv_bfloat16 g_ffh_l[(size_t)ROWS * FF];

// ======================= helpers ===================
__device__ __forceinline__ uint32_t smem_u32(const void* p) {
    uint32_t a;
    asm("{ .reg .u64 t; cvta.to.shared.u64 t, %1; cvt.u32.u64 %0, t; }"
        : "=r"(a) : "l"(p));
    return a;
}
__device__ __forceinline__ void mma_bf16(float* d,
    uint32_t a0, uint32_t a1, uint32_t a2, uint32_t a3, uint32_t b0, uint32_t b1)
{
    asm volatile(
        "mma.sync.aligned.m16n8k16.row.col.f32.bf16.bf16.f32 "
        "{%0,%1,%2,%3}, {%4,%5,%6,%7}, {%8,%9}, {%0,%1,%2,%3};"
        : "+f"(d[0]), "+f"(d[1]), "+f"(d[2]), "+f"(d[3])
        : "r"(a0), "r"(a1), "r"(a2), "r"(a3), "r"(b0), "r"(b1));
}
__device__ __forceinline__ void cp16(uint32_t dst, const void* src) {
    asm volatile("cp.async.cg.shared.global [%0], [%1], 16;" :: "r"(dst), "l"(src));
}
#define CP_COMMIT() asm volatile("cp.async.commit_group;" ::: "memory")
#define CP_WAIT1()  asm volatile("cp.async.wait_group 1;" ::: "memory")
#define CP_WAIT0()  asm volatile("cp.async.wait_group 0;" ::: "memory")

__device__ __forceinline__ uint32_t packbf(float x, float y) {
    __nv_bfloat162 t(__float2bfloat16(x), __float2bfloat16(y));
    return *reinterpret_cast<uint32_t*>(&t);
}

// =================== bf16x3/x2 tensor-core GEMM: C = A @ B^T ==================
// ALO=1: full bf16x3 (Ahi*Bhi + Ahi*Blo + Alo*Bhi). ALO=0: drop Alo term
// (bf16x2); Alo tile never loaded. Compile-time specialization.
#define RS 80
#define TB (128 * RS)
#define STAGE_BYTES (4 * TB)
#define SM_MMA_TOTAL (2 * STAGE_BYTES)

template<int ALO>
__global__ void __launch_bounds__(256, 2) tgemm(
    const __nv_bfloat16* __restrict__ Ahi, const __nv_bfloat16* __restrict__ Alo,
    const __nv_bfloat16* __restrict__ Bhi, const __nv_bfloat16* __restrict__ Blo,
    float* __restrict__ C, __nv_bfloat16* __restrict__ Chi,
    __nv_bfloat16* __restrict__ Clo,
    int Kdim, int lda, int ldb, int ldc, int relu)
{
    extern __shared__ char smem[];
    uint32_t sb = smem_u32(smem);

    int tid = threadIdx.x;
    int wid = tid >> 5, lane = tid & 31;
    int gid = lane >> 2, tig = lane & 3;
    int warp_m = wid >> 1;
    int warp_n = wid & 1;
    int rowC0 = blockIdx.y * 128;
    int colC0 = blockIdx.x * 128;

    int lr   = tid >> 1;
    int seg2 = (tid & 1) * 2;

    float acc[2][8][4] = {};
    int nstages = Kdim >> 5;

    {
        const char* gAh = (const char*)(Ahi + (size_t)(rowC0 + lr) * lda) + seg2 * 16;
        const char* gBh = (const char*)(Bhi + (size_t)(colC0 + lr) * ldb) + seg2 * 16;
        const char* gBl = (const char*)(Blo + (size_t)(colC0 + lr) * ldb) + seg2 * 16;
        uint32_t s = sb + lr * RS + seg2 * 16;
        cp16(s,          gAh); cp16(s + 16,          gAh + 16);
        cp16(s + 2 * TB, gBh); cp16(s + 2 * TB + 16, gBh + 16);
        cp16(s + 3 * TB, gBl); cp16(s + 3 * TB + 16, gBl + 16);
        if (ALO) {
            const char* gAl = (const char*)(Alo + (size_t)(rowC0 + lr) * lda) + seg2 * 16;
            cp16(s + TB, gAl); cp16(s + TB + 16, gAl + 16);
        }
        CP_COMMIT();
    }

    for (int st = 0; st < nstages; st++) {
        if (st + 1 < nstages) {
            int k0 = (st + 1) << 5;
            uint32_t base = sb + ((st + 1) & 1) * STAGE_BYTES;
            const char* gAh = (const char*)(Ahi + (size_t)(rowC0 + lr) * lda + k0) + seg2 * 16;
            const char* gBh = (const char*)(Bhi + (size_t)(colC0 + lr) * ldb + k0) + seg2 * 16;
            const char* gBl = (const char*)(Blo + (size_t)(colC0 + lr) * ldb + k0) + seg2 * 16;
            uint32_t s = base + lr * RS + seg2 * 16;
            cp16(s,          gAh); cp16(s + 16,          gAh + 16);
            cp16(s + 2 * TB, gBh); cp16(s + 2 * TB + 16, gBh + 16);
            cp16(s + 3 * TB, gBl); cp16(s + 3 * TB + 16, gBl + 16);
            if (ALO) {
                const char* gAl = (const char*)(Alo + (size_t)(rowC0 + lr) * lda + k0) + seg2 * 16;
                cp16(s + TB, gAl); cp16(s + TB + 16, gAl + 16);
            }
            CP_COMMIT();
            CP_WAIT1();
        } else {
            CP_WAIT0();
        }
        __syncthreads();

        const char* buf = smem + (st & 1) * STAGE_BYTES;
#pragma unroll
        for (int ks = 0; ks < 2; ks++) {
            int kbyte = ks * 32 + tig * 4;
            uint32_t ah[2][4], al[2][4];
#pragma unroll
            for (int mi = 0; mi < 2; mi++) {
                const char* ra = buf + (warp_m * 32 + mi * 16 + gid) * RS + kbyte;
                ah[mi][0] = *(const uint32_t*)(ra);
                ah[mi][1] = *(const uint32_t*)(ra + 8 * RS);
                ah[mi][2] = *(const uint32_t*)(ra + 16);
                ah[mi][3] = *(const uint32_t*)(ra + 8 * RS + 16);
                if (ALO) {
                    al[mi][0] = *(const uint32_t*)(ra + TB);
                    al[mi][1] = *(const uint32_t*)(ra + TB + 8 * RS);
                    al[mi][2] = *(const uint32_t*)(ra + TB + 16);
                    al[mi][3] = *(const uint32_t*)(ra + TB + 8 * RS + 16);
                }
            }
#pragma unroll
            for (int ni = 0; ni < 8; ni++) {
                const char* rb = buf + 2 * TB + (warp_n * 64 + ni * 8 + gid) * RS + kbyte;
                uint32_t bh0 = *(const uint32_t*)(rb);
                uint32_t bh1 = *(const uint32_t*)(rb + 16);
                uint32_t bl0 = *(const uint32_t*)(rb + TB);
                uint32_t bl1 = *(const uint32_t*)(rb + TB + 16);
#pragma unroll
                for (int mi = 0; mi < 2; mi++) {
                    mma_bf16(acc[mi][ni], ah[mi][0], ah[mi][1], ah[mi][2], ah[mi][3], bh0, bh1);
                    mma_bf16(acc[mi][ni], ah[mi][0], ah[mi][1], ah[mi][2], ah[mi][3], bl0, bl1);
                    if (ALO)
                        mma_bf16(acc[mi][ni], al[mi][0], al[mi][1], al[mi][2], al[mi][3], bh0, bh1);
                }
            }
        }
        __syncthreads();
    }

#pragma unroll
    for (int mi = 0; mi < 2; mi++) {
        int row0 = rowC0 + warp_m * 32 + mi * 16 + gid;
        int colB = colC0 + warp_n * 64 + tig * 2;
#pragma unroll
        for (int half = 0; half < 2; half++) {
            int row = row0 + half * 8;
#pragma unroll
            for (int ni = 0; ni < 8; ni++) {
                float v0 = acc[mi][ni][half * 2 + 0];
                float v1 = acc[mi][ni][half * 2 + 1];
                if (relu) { v0 = fmaxf(v0, 0.f); v1 = fmaxf(v1, 0.f); }
                if (Chi) {
                    __nv_bfloat16 h0 = __float2bfloat16(v0);
                    __nv_bfloat16 h1 = __float2bfloat16(v1);
                    __nv_bfloat162 hv(h0, h1);
                    __nv_bfloat162 lv(__float2bfloat16(v0 - __bfloat162float(h0)),
                                      __float2bfloat16(v1 - __bfloat162float(h1)));
                    *(__nv_bfloat162*)(Chi + (size_t)row * ldc + colB + ni * 8) = hv;
                    *(__nv_bfloat162*)(Clo + (size_t)row * ldc + colB + ni * 8) = lv;
                } else {
                    *(float2*)(C + (size_t)row * ldc + colB + ni * 8) = make_float2(v0, v1);
                }
            }
        }
    }
}

// ======================= flash attention ======================================
// S = (Qhi+Qlo)*Khi, O = (Phi+Plo)*Vhi. Output: vals hi only.
#define FTK 64
#define RSQ 272
#define RSV 144
#define SZ_Q (128 * RSQ)
#define SZ_K (64 * RSQ)
#define SZ_V (128 * RSV)
#define OFF_QH 0
#define OFF_QL SZ_Q
#define OFF_BUF (2 * SZ_Q)
#define BUF_SZ (SZ_K + SZ_V)
#define B_KH 0
#define B_VH SZ_K
#define SM_FLASH (OFF_BUF + 2 * BUF_SZ)  // 141312

__global__ void __launch_bounds__(256) fattn(
    const __nv_bfloat16* __restrict__ Qh, const __nv_bfloat16* __restrict__ Ql,
    const __nv_bfloat16* __restrict__ Kh,
    const __nv_bfloat16* __restrict__ VTh,
    __nv_bfloat16* __restrict__ Oh)
{
    extern __shared__ char smem[];
    uint32_t sb = smem_u32(smem);

    int tid = threadIdx.x;
    int wid = tid >> 5, lane = tid & 31;
    int gid = lane >> 2, tig = lane & 3;
    int q0 = blockIdx.x * 128;
    int bh = blockIdx.y;
    int b = bh >> 3, h = bh & 7;

    const __nv_bfloat16* qh_g = Qh + (size_t)bh * SS * HD;
    const __nv_bfloat16* ql_g = Ql + (size_t)bh * SS * HD;
    const __nv_bfloat16* kh_g = Kh + (size_t)bh * SS * HD;
    const __nv_bfloat16* vh_g = VTh + (size_t)bh * HD * SS;

    for (int i = tid; i < 128 * 16; i += 256) {
        int r = i >> 4, sg = i & 15;
        cp16(sb + OFF_QH + r * RSQ + sg * 16, qh_g + (size_t)(q0 + r) * HD + sg * 8);
        cp16(sb + OFF_QL + r * RSQ + sg * 16, ql_g + (size_t)(q0 + r) * HD + sg * 8);
    }
    {
        uint32_t bbuf = sb + OFF_BUF;
        for (int i = tid; i < 64 * 16; i += 256) {
            int r = i >> 4, sg = i & 15;
            cp16(bbuf + B_KH + r * RSQ + sg * 16, kh_g + (size_t)r * HD + sg * 8);
        }
        for (int i = tid; i < 128 * 8; i += 256) {
            int r = i >> 3, sg = i & 7;
            cp16(bbuf + B_VH + r * RSV + sg * 16, vh_g + (size_t)r * SS + sg * 8);
        }
    }
    CP_COMMIT();

    float oacc[16][4] = {};
    float m0 = -1e30f, m1 = -1e30f, l0 = 0.f, l1 = 0.f;

    const int NIT = SS / FTK;
    for (int it = 0; it < NIT; it++) {
        if (it + 1 < NIT) {
            int kv0 = (it + 1) * FTK;
            uint32_t bbuf = sb + OFF_BUF + ((it + 1) & 1) * BUF_SZ;
            for (int i = tid; i < 64 * 16; i += 256) {
                int r = i >> 4, sg = i & 15;
                cp16(bbuf + B_KH + r * RSQ + sg * 16, kh_g + (size_t)(kv0 + r) * HD + sg * 8);
            }
            for (int i = tid; i < 128 * 8; i += 256) {
                int r = i >> 3, sg = i & 7;
                cp16(bbuf + B_VH + r * RSV + sg * 16, vh_g + (size_t)r * SS + kv0 + sg * 8);
            }
            CP_COMMIT();
            CP_WAIT1();
        } else {
            CP_WAIT0();
        }
        __syncthreads();

        const char* buf = smem + OFF_BUF + (it & 1) * BUF_SZ;
        const char* qbh = smem + OFF_QH;
        const char* qbl = smem + OFF_QL;

        float s[8][4] = {};
#pragma unroll
        for (int kc = 0; kc < 8; kc++) {
            int kbyte = kc * 32 + tig * 4;
            const char* ra = qbh + (wid * 16 + gid) * RSQ + kbyte;
            const char* rl = qbl + (wid * 16 + gid) * RSQ + kbyte;
            uint32_t ah0 = *(const uint32_t*)(ra);
            uint32_t ah1 = *(const uint32_t*)(ra + 8 * RSQ);
            uint32_t ah2 = *(const uint32_t*)(ra + 16);
            uint32_t ah3 = *(const uint32_t*)(ra + 8 * RSQ + 16);
            uint32_t al0 = *(const uint32_t*)(rl);
            uint32_t al1 = *(const uint32_t*)(rl + 8 * RSQ);
            uint32_t al2 = *(const uint32_t*)(rl + 16);
            uint32_t al3 = *(const uint32_t*)(rl + 8 * RSQ + 16);
#pragma unroll
            for (int nt = 0; nt < 8; nt++) {
                const char* rb = buf + B_KH + (nt * 8 + gid) * RSQ + kbyte;
                uint32_t bh0 = *(const uint32_t*)(rb);
                uint32_t bh1 = *(const uint32_t*)(rb + 16);
                mma_bf16(s[nt], ah0, ah1, ah2, ah3, bh0, bh1);
                mma_bf16(s[nt], al0, al1, al2, al3, bh0, bh1);
            }
        }

        float ms0 = -1e30f, ms1 = -1e30f;
#pragma unroll
        for (int nt = 0; nt < 8; nt++) {
            ms0 = fmaxf(ms0, fmaxf(s[nt][0], s[nt][1]));
            ms1 = fmaxf(ms1, fmaxf(s[nt][2], s[nt][3]));
        }
        ms0 = fmaxf(ms0, __shfl_xor_sync(0xffffffffu, ms0, 1));
        ms0 = fmaxf(ms0, __shfl_xor_sync(0xffffffffu, ms0, 2));
        ms1 = fmaxf(ms1, __shfl_xor_sync(0xffffffffu, ms1, 1));
        ms1 = fmaxf(ms1, __shfl_xor_sync(0xffffffffu, ms1, 2));
        float mn0 = fmaxf(m0, ms0 * SCALE);
        float mn1 = fmaxf(m1, ms1 * SCALE);
        float a0 = __expf(m0 - mn0);
        float a1 = __expf(m1 - mn1);
        float r0 = 0.f, r1 = 0.f;
#pragma unroll
        for (int nt = 0; nt < 8; nt++) {
            s[nt][0] = __expf(fmaf(s[nt][0], SCALE, -mn0));
            s[nt][1] = __expf(fmaf(s[nt][1], SCALE, -mn0));
            s[nt][2] = __expf(fmaf(s[nt][2], SCALE, -mn1));
            s[nt][3] = __expf(fmaf(s[nt][3], SCALE, -mn1));
            r0 += s[nt][0] + s[nt][1];
            r1 += s[nt][2] + s[nt][3];
        }
        r0 += __shfl_xor_sync(0xffffffffu, r0, 1);
        r0 += __shfl_xor_sync(0xffffffffu, r0, 2);
        r1 += __shfl_xor_sync(0xffffffffu, r1, 1);
        r1 += __shfl_xor_sync(0xffffffffu, r1, 2);
        l0 = l0 * a0 + r0;
        l1 = l1 * a1 + r1;
        m0 = mn0; m1 = mn1;
#pragma unroll
        for (int nd = 0; nd < 16; nd++) {
            oacc[nd][0] *= a0; oacc[nd][1] *= a0;
            oacc[nd][2] *= a1; oacc[nd][3] *= a1;
        }

#pragma unroll
        for (int t = 0; t < 4; t++) {
            float p00 = s[2 * t][0],     p01 = s[2 * t][1];
            float p10 = s[2 * t][2],     p11 = s[2 * t][3];
            float p20 = s[2 * t + 1][0], p21 = s[2 * t + 1][1];
            float p30 = s[2 * t + 1][2], p31 = s[2 * t + 1][3];
            uint32_t ph0 = packbf(p00, p01);
            uint32_t ph1 = packbf(p10, p11);
            uint32_t ph2 = packbf(p20, p21);
            uint32_t ph3 = packbf(p30, p31);
            __nv_bfloat162 h0 = *reinterpret_cast<__nv_bfloat162*>(&ph0);
            __nv_bfloat162 h1 = *reinterpret_cast<__nv_bfloat162*>(&ph1);
            __nv_bfloat162 h2 = *reinterpret_cast<__nv_bfloat162*>(&ph2);
            __nv_bfloat162 h3 = *reinterpret_cast<__nv_bfloat162*>(&ph3);
            uint32_t pl0 = packbf(p00 - __bfloat162float(h0.x), p01 - __bfloat162float(h0.y));
            uint32_t pl1 = packbf(p10 - __bfloat162float(h1.x), p11 - __bfloat162float(h1.y));
            uint32_t pl2 = packbf(p20 - __bfloat162float(h2.x), p21 - __bfloat162float(h2.y));
            uint32_t pl3 = packbf(p30 - __bfloat162float(h3.x), p31 - __bfloat162float(h3.y));
            int kbyte = t * 32 + tig * 4;
#pragma unroll
            for (int nd = 0; nd < 16; nd++) {
                const char* rb = buf + B_VH + (nd * 8 + gid) * RSV + kbyte;
                uint32_t vh0 = *(const uint32_t*)(rb);
                uint32_t vh1 = *(const uint32_t*)(rb + 16);
                mma_bf16(oacc[nd], ph0, ph1, ph2, ph3, vh0, vh1);
                mma_bf16(oacc[nd], pl0, pl1, pl2, pl3, vh0, vh1);
            }
        }
        __syncthreads();
    }

    float inv0 = 1.0f / l0, inv1 = 1.0f / l1;
    int row0 = b * SS + q0 + wid * 16 + gid;
    int colB = h * HD + tig * 2;
#pragma unroll
    for (int nd = 0; nd < 16; nd++) {
#pragma unroll
        for (int half = 0; half < 2; half++) {
            float v0 = oacc[nd][half * 2 + 0] * (half ? inv1 : inv0);
            float v1 = oacc[nd][half * 2 + 1] * (half ? inv1 : inv0);
            __nv_bfloat162 hv(__float2bfloat16(v0), __float2bfloat16(v1));
            size_t addr = (size_t)(row0 + half * 8) * DD + colB + nd * 8;
            *(__nv_bfloat162*)(Oh + addr) = hv;
        }
    }
}

// ---------------- split fp32 -> hi/lo bf16, flat ------------------------------
__global__ void __launch_bounds__(256) split_flat(
    const float* __restrict__ in, __nv_bfloat16* __restrict__ hi,
    __nv_bfloat16* __restrict__ lo, long long n4)
{
    long long i = (long long)blockIdx.x * 256 + threadIdx.x;
    if (i >= n4) return;
    float4 v = ((const float4*)in)[i];
    __nv_bfloat16 h0 = __float2bfloat16(v.x), h1 = __float2bfloat16(v.y);
    __nv_bfloat16 h2 = __float2bfloat16(v.z), h3 = __float2bfloat16(v.w);
    __nv_bfloat162* H = (__nv_bfloat162*)hi;
    __nv_bfloat162* L = (__nv_bfloat162*)lo;
    H[2 * i]     = __nv_bfloat162(h0, h1);
    H[2 * i + 1] = __nv_bfloat162(h2, h3);
    L[2 * i]     = __nv_bfloat162(__float2bfloat16(v.x - __bfloat162float(h0)),
                                  __float2bfloat16(v.y - __bfloat162float(h1)));
    L[2 * i + 1] = __nv_bfloat162(__float2bfloat16(v.z - __bfloat162float(h2)),
                                  __float2bfloat16(v.w - __bfloat162float(h3)));
}

// --------- fused weight splits ------------------------------------------------
__global__ void __launch_bounds__(256) split_weights(
    const float* __restrict__ Wqkv, const float* __restrict__ Wo,
    const float* __restrict__ W1,   const float* __restrict__ W2,
    __nv_bfloat16* __restrict__ qkv_h, __nv_bfloat16* __restrict__ qkv_l,
    __nv_bfloat16* __restrict__ wo_h,  __nv_bfloat16* __restrict__ wo_l,
    __nv_bfloat16* __restrict__ w1_h,  __nv_bfloat16* __restrict__ w1_l,
    __nv_bfloat16* __restrict__ w2_h,  __nv_bfloat16* __restrict__ w2_l)
{
    int bid = blockIdx.x;
    const float* W; __nv_bfloat16 *hi, *lo; int K, N, nbx, local;
    if (bid < 3072)      { W = Wqkv; hi = qkv_h; lo = qkv_l; K = DD; N = 3 * DD; nbx = 96;  local = bid; }
    else if (bid < 4096) { W = Wo;   hi = wo_h;  lo = wo_l;  K = DD; N = DD;     nbx = 32;  local = bid - 3072; }
    else if (bid < 8192) { W = W1;   hi = w1_h;  lo = w1_l;  K = DD; N = FF;     nbx = 128; local = bid - 4096; }
    else                 { W = W2;   hi = w2_h;  lo = w2_l;  K = FF; N = DD;     nbx = 32;  local = bid - 8192; }
    int n0 = (local % nbx) * 32, k0 = (local / nbx) * 32;

    __shared__ float t[32][33];
    int tx = threadIdx.x & 31, ty = threadIdx.x >> 5;
#pragma unroll
    for (int dy = 0; dy < 32; dy += 8)
        t[ty + dy][tx] = W[(size_t)(k0 + ty + dy) * N + n0 + tx];
    __syncthreads();
#pragma unroll
    for (int dy = 0; dy < 32; dy += 8) {
        int n = n0 + ty + dy, k = k0 + tx;
        float v = t[tx][ty + dy];
        __nv_bfloat16 h = __float2bfloat16(v);
        hi[(size_t)n * K + k] = h;
        lo[(size_t)n * K + k] = __float2bfloat16(v - __bfloat162float(h));
    }
}

// ------------- split qkv -> Q(hi/lo), K(hi) arrays [bh][s][hd] ----------------
__global__ void __launch_bounds__(256) split_qk(
    const float* __restrict__ qkv,
    __nv_bfloat16* __restrict__ Qh, __nv_bfloat16* __restrict__ Ql,
    __nv_bfloat16* __restrict__ Kh)
{
    int part = blockIdx.y;
    long long i = (long long)blockIdx.x * 256 + threadIdx.x;
    long long r = i >> 5;
    int hd = (int)(i & 31) * 4;
    int bh = (int)(r / SS);
    int s_ = (int)(r % SS);
    int b = bh >> 3, h = bh & 7;
    const float* src = qkv + ((size_t)(b * SS + s_)) * 3072 + h * 384 + part * 128 + hd;
    float4 v = *(const float4*)src;
    __nv_bfloat16 h0 = __float2bfloat16(v.x), h1 = __float2bfloat16(v.y);
    __nv_bfloat16 h2 = __float2bfloat16(v.z), h3 = __float2bfloat16(v.w);
    __nv_bfloat162 hv0(h0, h1), hv1(h2, h3);
    size_t o = ((size_t)bh * SS + s_) * HD + hd;
    if (part == 0) {
        __nv_bfloat162 lv0(__float2bfloat16(v.x - __bfloat162float(h0)),
                           __float2bfloat16(v.y - __bfloat162float(h1)));
        __nv_bfloat162 lv1(__float2bfloat16(v.z - __bfloat162float(h2)),
                           __float2bfloat16(v.w - __bfloat162float(h3)));
        *(__nv_bfloat162*)(Qh + o)     = hv0;
        *(__nv_bfloat162*)(Qh + o + 2) = hv1;
        *(__nv_bfloat162*)(Ql + o)     = lv0;
        *(__nv_bfloat162*)(Ql + o + 2) = lv1;
    } else {
        *(__nv_bfloat162*)(Kh + o)     = hv0;
        *(__nv_bfloat162*)(Kh + o + 2) = hv1;
    }
}

// ------------- split + transpose V -> VT [bh][hd][s] (hi only) ----------------
__global__ void __launch_bounds__(256) splitTv(
    const float* __restrict__ qkv,
    __nv_bfloat16* __restrict__ VTh)
{
    __shared__ float t[32][33];
    int s0 = blockIdx.x * 32, hd0 = blockIdx.y * 32;
    int bh = blockIdx.z;
    int b = bh >> 3, h = bh & 7;
    int tx = threadIdx.x & 31, ty = threadIdx.x >> 5;
#pragma unroll
    for (int dy = 0; dy < 32; dy += 8)
        t[ty + dy][tx] = qkv[((size_t)(b * SS + s0 + ty + dy)) * 3072 + h * 384 + 256 + hd0 + tx];
    __syncthreads();
#pragma unroll
    for (int dy = 0; dy < 32; dy += 8) {
        int hd = hd0 + ty + dy, s_ = s0 + tx;
        float v = t[tx][ty + dy];
        size_t o = ((size_t)bh * HD + hd) * SS + s_;
        VTh[o] = __float2bfloat16(v);
    }
}

// ------------- fused residual add + LayerNorm (+ optional split) --------------
__global__ void __launch_bounds__(256) add_ln(
    const float* __restrict__ X, const float* __restrict__ R, float* __restrict__ O,
    __nv_bfloat16* __restrict__ Ohi, __nv_bfloat16* __restrict__ Olo)
{
    long long row = blockIdx.x;
    const float* x = X + row * DD;
    const float* r = R + row * DD;
    int tid = threadIdx.x;

    __shared__ float rs[256], rss[256];

    float v[4];
    float s = 0.f, ss2 = 0.f;
#pragma unroll
    for (int i = 0; i < 4; i++) {
        float y = x[tid + i * 256] + r[tid + i * 256];
        v[i] = y;
        s += y;
        ss2 += y * y;
    }
    rs[tid] = s; rss[tid] = ss2;
    __syncthreads();
    for (int st = 128; st > 0; st >>= 1) {
        if (tid < st) { rs[tid] += rs[tid + st]; rss[tid] += rss[tid + st]; }
        __syncthreads();
    }
    float mean = rs[0] * (1.0f / DD);
    float var  = rss[0] * (1.0f / DD) - mean * mean;
    float inv  = rsqrtf(var + EPS);
#pragma unroll
    for (int i = 0; i < 4; i++) {
        float y = (v[i] - mean) * inv;
        O[row * DD + tid + i * 256] = y;
        if (Ohi) {
            __nv_bfloat16 hb = __float2bfloat16(y);
            Ohi[row * DD + tid + i * 256] = hb;
            Olo[row * DD + tid + i * 256] = __float2bfloat16(y - __bfloat162float(hb));
        }
    }
}

// ------------------------------- launcher -------------------------------------
extern "C" void kernel_launch(void* const* d_in, const int* in_sizes, int n_in,
                              void* d_out, int out_size)
{
    const float* x    = (const float*)d_in[0];
    const float* Wqkv = (const float*)d_in[1];
    const float* Wo   = (const float*)d_in[2];
    const float* W1   = (const float*)d_in[3];
    const float* W2   = (const float*)d_in[4];
    float* out = (float*)d_out;

    float *qkv, *attn, *x1, *ffo;
    cudaGetSymbolAddress((void**)&qkv,  g_qkv);
    cudaGetSymbolAddress((void**)&attn, g_attn);
    cudaGetSymbolAddress((void**)&x1,   g_x1);
    cudaGetSymbolAddress((void**)&ffo,  g_ffo);

    __nv_bfloat16 *xs_h, *xs_l, *wqkv_h, *wqkv_l, *wo_h, *wo_l, *w1_h, *w1_l,
                  *w2_h, *w2_l, *qh, *ql, *kh, *vth,
                  *vls_h, *x1s_h, *x1s_l, *ffh_h, *ffh_l;
    cudaGetSymbolAddress((void**)&xs_h,   g_xs_h);
    cudaGetSymbolAddress((void**)&xs_l,   g_xs_l);
    cudaGetSymbolAddress((void**)&wqkv_h, g_wqkv_h);
    cudaGetSymbolAddress((void**)&wqkv_l, g_wqkv_l);
    cudaGetSymbolAddress((void**)&wo_h,   g_wo_h);
    cudaGetSymbolAddress((void**)&wo_l,   g_wo_l);
    cudaGetSymbolAddress((void**)&w1_h,   g_w1_h);
    cudaGetSymbolAddress((void**)&w1_l,   g_w1_l);
    cudaGetSymbolAddress((void**)&w2_h,   g_w2_h);
    cudaGetSymbolAddress((void**)&w2_l,   g_w2_l);
    cudaGetSymbolAddress((void**)&qh,     g_qh);
    cudaGetSymbolAddress((void**)&ql,     g_ql);
    cudaGetSymbolAddress((void**)&kh,     g_kh);
    cudaGetSymbolAddress((void**)&vth,    g_vth);
    cudaGetSymbolAddress((void**)&vls_h,  g_vls_h);
    cudaGetSymbolAddress((void**)&x1s_h,  g_x1s_h);
    cudaGetSymbolAddress((void**)&x1s_l,  g_x1s_l);
    cudaGetSymbolAddress((void**)&ffh_h,  g_ffh_h);
    cudaGetSymbolAddress((void**)&ffh_l,  g_ffh_l);

    cudaFuncSetAttribute(tgemm<0>, cudaFuncAttributeMaxDynamicSharedMemorySize, SM_MMA_TOTAL);
    cudaFuncSetAttribute(tgemm<1>, cudaFuncAttributeMaxDynamicSharedMemorySize, SM_MMA_TOTAL);
    cudaFuncSetAttribute(fattn, cudaFuncAttributeMaxDynamicSharedMemorySize, SM_FLASH);

    split_weights<<<12288, 256>>>(Wqkv, Wo, W1, W2,
        wqkv_h, wqkv_l, wo_h, wo_l, w1_h, w1_l, w2_h, w2_l);
    split_flat<<<(long long)ROWS * DD / 1024, 256>>>(x, xs_h, xs_l, (long long)ROWS * DD / 4);

    // 1) QKV = x @ Wqkv (bf16x2)
    tgemm<0><<<dim3(3 * DD / 128, ROWS / 128), 256, SM_MMA_TOTAL>>>(
        xs_h, xs_l, wqkv_h, wqkv_l, qkv, nullptr, nullptr, DD, DD, DD, 3 * DD, 0);

    // 2) split qkv into attention operands (Q hi/lo, K hi, VT hi)
    split_qk<<<dim3((unsigned)((long long)BB * HH * SS * HD / 4 / 256), 2), 256>>>(
        qkv, qh, ql, kh);
    splitTv<<<dim3(SS / 32, HD / 32, BB * HH), 256>>>(qkv, vth);

    // 3) flash attention -> vals hi
    fattn<<<dim3(SS / 128, BB * HH), 256, SM_FLASH>>>(
        qh, ql, kh, vth, vls_h);

    // 4) attn = vals @ Wo (bf16x2)
    tgemm<0><<<dim3(DD / 128, ROWS / 128), 256, SM_MMA_TOTAL>>>(
        vls_h, vls_h, wo_h, wo_l, attn, nullptr, nullptr, DD, DD, DD, DD, 0);

    // 5) x1 = LN(x + attn), fused split
    add_ln<<<ROWS, 256>>>(x, attn, x1, x1s_h, x1s_l);

    // 6) ffh = relu(x1 @ W1), hi/lo out (full bf16x3)
    tgemm<1><<<dim3(FF / 128, ROWS / 128), 256, SM_MMA_TOTAL>>>(
        x1s_h, x1s_l, w1_h, w1_l, nullptr, ffh_h, ffh_l, DD, DD, DD, FF, 1);

    // 7) ffo = ffh @ W2 (full bf16x3)
    tgemm<1><<<dim3(DD / 128, ROWS / 128), 256, SM_MMA_TOTAL>>>(
        ffh_h, ffh_l, w2_h, w2_l, ffo, nullptr, nullptr, FF, FF, FF, DD, 0);

    // 8) out = LN(x1 + ffo)
    add_ln<<<ROWS, 256>>>(x1, ffo, out, nullptr, nullptr);
}

// round 16
// speedup vs baseline: 1.2528x; 1.1452x over previous
#include <cuda_runtime.h>
#include <cuda_bf16.h>
#include <cstdint>
#include <cstddef>

#define BB 4
#define SS 2048
#define DD 1024
#define HH 8
#define HD 128
#define FF 4096
#define ROWS (BB * SS)
#define SCALE 0.08838834764831843f
#define EPS 1e-5f

// ---------------- scratch ----------------
__device__ float g_qkv [(size_t)ROWS * 3 * DD];
__device__ float g_attn[(size_t)ROWS * DD];
__device__ float g_x1  [(size_t)ROWS * DD];
__device__ float g_ffo [(size_t)ROWS * DD];

__device__ __nv_bfloat16 g_xs_h [(size_t)ROWS * DD];
__device__ __nv_bfloat16 g_xs_l [(size_t)ROWS * DD];
__device__ __nv_bfloat16 g_wqkv_h[(size_t)3 * DD * DD];
__device__ __nv_bfloat16 g_wqkv_l[(size_t)3 * DD * DD];
__device__ __nv_bfloat16 g_wo_h [(size_t)DD * DD];
__device__ __nv_bfloat16 g_wo_l [(size_t)DD * DD];
__device__ __nv_bfloat16 g_w1_h [(size_t)FF * DD];
__device__ __nv_bfloat16 g_w1_l [(size_t)FF * DD];
__device__ __nv_bfloat16 g_w2_h [(size_t)DD * FF];
__device__ __nv_bfloat16 g_w2_l [(size_t)DD * FF];
__device__ __nv_bfloat16 g_qh [(size_t)BB * HH * SS * HD];
__device__ __nv_bfloat16 g_kh [(size_t)BB * HH * SS * HD];
__device__ __nv_bfloat16 g_vth[(size_t)BB * HH * HD * SS];
__device__ __nv_bfloat16 g_vls_h[(size_t)ROWS * DD];
__device__ __nv_bfloat16 g_x1s_h[(size_t)ROWS * DD];
__device__ __nv_bfloat16 g_x1s_l[(size_t)ROWS * DD];
__device__ __nv_bfloat16 g_ffh_h[(size_t)ROWS * FF];
__device__ __nv_bfloat16 g_ffh_l[(size_t)ROWS * FF];

// ======================= helpers ===================
__device__ __forceinline__ uint32_t smem_u32(const void* p) {
    uint32_t a;
    asm("{ .reg .u64 t; cvta.to.shared.u64 t, %1; cvt.u32.u64 %0, t; }"
        : "=r"(a) : "l"(p));
    return a;
}
__device__ __forceinline__ void mma_bf16(float* d,
    uint32_t a0, uint32_t a1, uint32_t a2, uint32_t a3, uint32_t b0, uint32_t b1)
{
    asm volatile(
        "mma.sync.aligned.m16n8k16.row.col.f32.bf16.bf16.f32 "
        "{%0,%1,%2,%3}, {%4,%5,%6,%7}, {%8,%9}, {%0,%1,%2,%3};"
        : "+f"(d[0]), "+f"(d[1]), "+f"(d[2]), "+f"(d[3])
        : "r"(a0), "r"(a1), "r"(a2), "r"(a3), "r"(b0), "r"(b1));
}
__device__ __forceinline__ void cp16(uint32_t dst, const void* src) {
    asm volatile("cp.async.cg.shared.global [%0], [%1], 16;" :: "r"(dst), "l"(src));
}
#define CP_COMMIT() asm volatile("cp.async.commit_group;" ::: "memory")
#define CP_WAIT1()  asm volatile("cp.async.wait_group 1;" ::: "memory")
#define CP_WAIT0()  asm volatile("cp.async.wait_group 0;" ::: "memory")

__device__ __forceinline__ uint32_t packbf(float x, float y) {
    __nv_bfloat162 t(__float2bfloat16(x), __float2bfloat16(y));
    return *reinterpret_cast<uint32_t*>(&t);
}

// =================== bf16x3/x2 tensor-core GEMM: C = A @ B^T ==================
#define RS 80
#define TB (128 * RS)
#define STAGE_BYTES (4 * TB)
#define SM_MMA_TOTAL (2 * STAGE_BYTES)

template<int ALO>
__global__ void __launch_bounds__(256, 2) tgemm(
    const __nv_bfloat16* __restrict__ Ahi, const __nv_bfloat16* __restrict__ Alo,
    const __nv_bfloat16* __restrict__ Bhi, const __nv_bfloat16* __restrict__ Blo,
    float* __restrict__ C, __nv_bfloat16* __restrict__ Chi,
    __nv_bfloat16* __restrict__ Clo,
    int Kdim, int lda, int ldb, int ldc, int relu)
{
    extern __shared__ char smem[];
    uint32_t sb = smem_u32(smem);

    int tid = threadIdx.x;
    int wid = tid >> 5, lane = tid & 31;
    int gid = lane >> 2, tig = lane & 3;
    int warp_m = wid >> 1;
    int warp_n = wid & 1;
    int rowC0 = blockIdx.y * 128;
    int colC0 = blockIdx.x * 128;

    int lr   = tid >> 1;
    int seg2 = (tid & 1) * 2;

    float acc[2][8][4] = {};
    int nstages = Kdim >> 5;

    {
        const char* gAh = (const char*)(Ahi + (size_t)(rowC0 + lr) * lda) + seg2 * 16;
        const char* gBh = (const char*)(Bhi + (size_t)(colC0 + lr) * ldb) + seg2 * 16;
        const char* gBl = (const char*)(Blo + (size_t)(colC0 + lr) * ldb) + seg2 * 16;
        uint32_t s = sb + lr * RS + seg2 * 16;
        cp16(s,          gAh); cp16(s + 16,          gAh + 16);
        cp16(s + 2 * TB, gBh); cp16(s + 2 * TB + 16, gBh + 16);
        cp16(s + 3 * TB, gBl); cp16(s + 3 * TB + 16, gBl + 16);
        if (ALO) {
            const char* gAl = (const char*)(Alo + (size_t)(rowC0 + lr) * lda) + seg2 * 16;
            cp16(s + TB, gAl); cp16(s + TB + 16, gAl + 16);
        }
        CP_COMMIT();
    }

    for (int st = 0; st < nstages; st++) {
        if (st + 1 < nstages) {
            int k0 = (st + 1) << 5;
            uint32_t base = sb + ((st + 1) & 1) * STAGE_BYTES;
            const char* gAh = (const char*)(Ahi + (size_t)(rowC0 + lr) * lda + k0) + seg2 * 16;
            const char* gBh = (const char*)(Bhi + (size_t)(colC0 + lr) * ldb + k0) + seg2 * 16;
            const char* gBl = (const char*)(Blo + (size_t)(colC0 + lr) * ldb + k0) + seg2 * 16;
            uint32_t s = base + lr * RS + seg2 * 16;
            cp16(s,          gAh); cp16(s + 16,          gAh + 16);
            cp16(s + 2 * TB, gBh); cp16(s + 2 * TB + 16, gBh + 16);
            cp16(s + 3 * TB, gBl); cp16(s + 3 * TB + 16, gBl + 16);
            if (ALO) {
                const char* gAl = (const char*)(Alo + (size_t)(rowC0 + lr) * lda + k0) + seg2 * 16;
                cp16(s + TB, gAl); cp16(s + TB + 16, gAl + 16);
            }
            CP_COMMIT();
            CP_WAIT1();
        } else {
            CP_WAIT0();
        }
        __syncthreads();

        const char* buf = smem + (st & 1) * STAGE_BYTES;
#pragma unroll
        for (int ks = 0; ks < 2; ks++) {
            int kbyte = ks * 32 + tig * 4;
            uint32_t ah[2][4], al[2][4];
#pragma unroll
            for (int mi = 0; mi < 2; mi++) {
                const char* ra = buf + (warp_m * 32 + mi * 16 + gid) * RS + kbyte;
                ah[mi][0] = *(const uint32_t*)(ra);
                ah[mi][1] = *(const uint32_t*)(ra + 8 * RS);
                ah[mi][2] = *(const uint32_t*)(ra + 16);
                ah[mi][3] = *(const uint32_t*)(ra + 8 * RS + 16);
                if (ALO) {
                    al[mi][0] = *(const uint32_t*)(ra + TB);
                    al[mi][1] = *(const uint32_t*)(ra + TB + 8 * RS);
                    al[mi][2] = *(const uint32_t*)(ra + TB + 16);
                    al[mi][3] = *(const uint32_t*)(ra + TB + 8 * RS + 16);
                }
            }
#pragma unroll
            for (int ni = 0; ni < 8; ni++) {
                const char* rb = buf + 2 * TB + (warp_n * 64 + ni * 8 + gid) * RS + kbyte;
                uint32_t bh0 = *(const uint32_t*)(rb);
                uint32_t bh1 = *(const uint32_t*)(rb + 16);
                uint32_t bl0 = *(const uint32_t*)(rb + TB);
                uint32_t bl1 = *(const uint32_t*)(rb + TB + 16);
#pragma unroll
                for (int mi = 0; mi < 2; mi++) {
                    mma_bf16(acc[mi][ni], ah[mi][0], ah[mi][1], ah[mi][2], ah[mi][3], bh0, bh1);
                    mma_bf16(acc[mi][ni], ah[mi][0], ah[mi][1], ah[mi][2], ah[mi][3], bl0, bl1);
                    if (ALO)
                        mma_bf16(acc[mi][ni], al[mi][0], al[mi][1], al[mi][2], al[mi][3], bh0, bh1);
                }
            }
        }
        __syncthreads();
    }

#pragma unroll
    for (int mi = 0; mi < 2; mi++) {
        int row0 = rowC0 + warp_m * 32 + mi * 16 + gid;
        int colB = colC0 + warp_n * 64 + tig * 2;
#pragma unroll
        for (int half = 0; half < 2; half++) {
            int row = row0 + half * 8;
#pragma unroll
            for (int ni = 0; ni < 8; ni++) {
                float v0 = acc[mi][ni][half * 2 + 0];
                float v1 = acc[mi][ni][half * 2 + 1];
                if (relu) { v0 = fmaxf(v0, 0.f); v1 = fmaxf(v1, 0.f); }
                if (Chi) {
                    __nv_bfloat16 h0 = __float2bfloat16(v0);
                    __nv_bfloat16 h1 = __float2bfloat16(v1);
                    __nv_bfloat162 hv(h0, h1);
                    __nv_bfloat162 lv(__float2bfloat16(v0 - __bfloat162float(h0)),
                                      __float2bfloat16(v1 - __bfloat162float(h1)));
                    *(__nv_bfloat162*)(Chi + (size_t)row * ldc + colB + ni * 8) = hv;
                    *(__nv_bfloat162*)(Clo + (size_t)row * ldc + colB + ni * 8) = lv;
                } else {
                    *(float2*)(C + (size_t)row * ldc + colB + ni * 8) = make_float2(v0, v1);
                }
            }
        }
    }
}

// ======================= flash attention ======================================
// Pure bf16 attention: S = Qhi*Khi, O = Phi*Vhi (fp32 accum, exact softmax).
#define FTK 64
#define RSQ 272
#define RSV 144
#define SZ_Q (128 * RSQ)
#define SZ_K (64 * RSQ)
#define SZ_V (128 * RSV)
#define OFF_QH 0
#define OFF_BUF SZ_Q
#define BUF_SZ (SZ_K + SZ_V)
#define B_KH 0
#define B_VH SZ_K
#define SM_FLASH (OFF_BUF + 2 * BUF_SZ)  // 106496

__global__ void __launch_bounds__(256) fattn(
    const __nv_bfloat16* __restrict__ Qh,
    const __nv_bfloat16* __restrict__ Kh,
    const __nv_bfloat16* __restrict__ VTh,
    __nv_bfloat16* __restrict__ Oh)
{
    extern __shared__ char smem[];
    uint32_t sb = smem_u32(smem);

    int tid = threadIdx.x;
    int wid = tid >> 5, lane = tid & 31;
    int gid = lane >> 2, tig = lane & 3;
    int q0 = blockIdx.x * 128;
    int bh = blockIdx.y;
    int b = bh >> 3, h = bh & 7;

    const __nv_bfloat16* qh_g = Qh + (size_t)bh * SS * HD;
    const __nv_bfloat16* kh_g = Kh + (size_t)bh * SS * HD;
    const __nv_bfloat16* vh_g = VTh + (size_t)bh * HD * SS;

    for (int i = tid; i < 128 * 16; i += 256) {
        int r = i >> 4, sg = i & 15;
        cp16(sb + OFF_QH + r * RSQ + sg * 16, qh_g + (size_t)(q0 + r) * HD + sg * 8);
    }
    {
        uint32_t bbuf = sb + OFF_BUF;
        for (int i = tid; i < 64 * 16; i += 256) {
            int r = i >> 4, sg = i & 15;
            cp16(bbuf + B_KH + r * RSQ + sg * 16, kh_g + (size_t)r * HD + sg * 8);
        }
        for (int i = tid; i < 128 * 8; i += 256) {
            int r = i >> 3, sg = i & 7;
            cp16(bbuf + B_VH + r * RSV + sg * 16, vh_g + (size_t)r * SS + sg * 8);
        }
    }
    CP_COMMIT();

    float oacc[16][4] = {};
    float m0 = -1e30f, m1 = -1e30f, l0 = 0.f, l1 = 0.f;

    const int NIT = SS / FTK;
    for (int it = 0; it < NIT; it++) {
        if (it + 1 < NIT) {
            int kv0 = (it + 1) * FTK;
            uint32_t bbuf = sb + OFF_BUF + ((it + 1) & 1) * BUF_SZ;
            for (int i = tid; i < 64 * 16; i += 256) {
                int r = i >> 4, sg = i & 15;
                cp16(bbuf + B_KH + r * RSQ + sg * 16, kh_g + (size_t)(kv0 + r) * HD + sg * 8);
            }
            for (int i = tid; i < 128 * 8; i += 256) {
                int r = i >> 3, sg = i & 7;
                cp16(bbuf + B_VH + r * RSV + sg * 16, vh_g + (size_t)r * SS + kv0 + sg * 8);
            }
            CP_COMMIT();
            CP_WAIT1();
        } else {
            CP_WAIT0();
        }
        __syncthreads();

        const char* buf = smem + OFF_BUF + (it & 1) * BUF_SZ;
        const char* qbh = smem + OFF_QH;

        float s[8][4] = {};
#pragma unroll
        for (int kc = 0; kc < 8; kc++) {
            int kbyte = kc * 32 + tig * 4;
            const char* ra = qbh + (wid * 16 + gid) * RSQ + kbyte;
            uint32_t ah0 = *(const uint32_t*)(ra);
            uint32_t ah1 = *(const uint32_t*)(ra + 8 * RSQ);
            uint32_t ah2 = *(const uint32_t*)(ra + 16);
            uint32_t ah3 = *(const uint32_t*)(ra + 8 * RSQ + 16);
#pragma unroll
            for (int nt = 0; nt < 8; nt++) {
                const char* rb = buf + B_KH + (nt * 8 + gid) * RSQ + kbyte;
                uint32_t bh0 = *(const uint32_t*)(rb);
                uint32_t bh1 = *(const uint32_t*)(rb + 16);
                mma_bf16(s[nt], ah0, ah1, ah2, ah3, bh0, bh1);
            }
        }

        float ms0 = -1e30f, ms1 = -1e30f;
#pragma unroll
        for (int nt = 0; nt < 8; nt++) {
            ms0 = fmaxf(ms0, fmaxf(s[nt][0], s[nt][1]));
            ms1 = fmaxf(ms1, fmaxf(s[nt][2], s[nt][3]));
        }
        ms0 = fmaxf(ms0, __shfl_xor_sync(0xffffffffu, ms0, 1));
        ms0 = fmaxf(ms0, __shfl_xor_sync(0xffffffffu, ms0, 2));
        ms1 = fmaxf(ms1, __shfl_xor_sync(0xffffffffu, ms1, 1));
        ms1 = fmaxf(ms1, __shfl_xor_sync(0xffffffffu, ms1, 2));
        float mn0 = fmaxf(m0, ms0 * SCALE);
        float mn1 = fmaxf(m1, ms1 * SCALE);
        float a0 = __expf(m0 - mn0);
        float a1 = __expf(m1 - mn1);
        float r0 = 0.f, r1 = 0.f;
#pragma unroll
        for (int nt = 0; nt < 8; nt++) {
            s[nt][0] = __expf(fmaf(s[nt][0], SCALE, -mn0));
            s[nt][1] = __expf(fmaf(s[nt][1], SCALE, -mn0));
            s[nt][2] = __expf(fmaf(s[nt][2], SCALE, -mn1));
            s[nt][3] = __expf(fmaf(s[nt][3], SCALE, -mn1));
            r0 += s[nt][0] + s[nt][1];
            r1 += s[nt][2] + s[nt][3];
        }
        r0 += __shfl_xor_sync(0xffffffffu, r0, 1);
        r0 += __shfl_xor_sync(0xffffffffu, r0, 2);
        r1 += __shfl_xor_sync(0xffffffffu, r1, 1);
        r1 += __shfl_xor_sync(0xffffffffu, r1, 2);
        l0 = l0 * a0 + r0;
        l1 = l1 * a1 + r1;
        m0 = mn0; m1 = mn1;
#pragma unroll
        for (int nd = 0; nd < 16; nd++) {
            oacc[nd][0] *= a0; oacc[nd][1] *= a0;
            oacc[nd][2] *= a1; oacc[nd][3] *= a1;
        }

#pragma unroll
        for (int t = 0; t < 4; t++) {
            uint32_t ph0 = packbf(s[2 * t][0],     s[2 * t][1]);
            uint32_t ph1 = packbf(s[2 * t][2],     s[2 * t][3]);
            uint32_t ph2 = packbf(s[2 * t + 1][0], s[2 * t + 1][1]);
            uint32_t ph3 = packbf(s[2 * t + 1][2], s[2 * t + 1][3]);
            int kbyte = t * 32 + tig * 4;
#pragma unroll
            for (int nd = 0; nd < 16; nd++) {
                const char* rb = buf + B_VH + (nd * 8 + gid) * RSV + kbyte;
                uint32_t vh0 = *(const uint32_t*)(rb);
                uint32_t vh1 = *(const uint32_t*)(rb + 16);
                mma_bf16(oacc[nd], ph0, ph1, ph2, ph3, vh0, vh1);
            }
        }
        __syncthreads();
    }

    float inv0 = 1.0f / l0, inv1 = 1.0f / l1;
    int row0 = b * SS + q0 + wid * 16 + gid;
    int colB = h * HD + tig * 2;
#pragma unroll
    for (int nd = 0; nd < 16; nd++) {
#pragma unroll
        for (int half = 0; half < 2; half++) {
            float v0 = oacc[nd][half * 2 + 0] * (half ? inv1 : inv0);
            float v1 = oacc[nd][half * 2 + 1] * (half ? inv1 : inv0);
            __nv_bfloat162 hv(__float2bfloat16(v0), __float2bfloat16(v1));
            size_t addr = (size_t)(row0 + half * 8) * DD + colB + nd * 8;
            *(__nv_bfloat162*)(Oh + addr) = hv;
        }
    }
}

// ---------------- split fp32 -> hi/lo bf16, flat ------------------------------
__global__ void __launch_bounds__(256) split_flat(
    const float* __restrict__ in, __nv_bfloat16* __restrict__ hi,
    __nv_bfloat16* __restrict__ lo, long long n4)
{
    long long i = (long long)blockIdx.x * 256 + threadIdx.x;
    if (i >= n4) return;
    float4 v = ((const float4*)in)[i];
    __nv_bfloat16 h0 = __float2bfloat16(v.x), h1 = __float2bfloat16(v.y);
    __nv_bfloat16 h2 = __float2bfloat16(v.z), h3 = __float2bfloat16(v.w);
    __nv_bfloat162* H = (__nv_bfloat162*)hi;
    __nv_bfloat162* L = (__nv_bfloat162*)lo;
    H[2 * i]     = __nv_bfloat162(h0, h1);
    H[2 * i + 1] = __nv_bfloat162(h2, h3);
    L[2 * i]     = __nv_bfloat162(__float2bfloat16(v.x - __bfloat162float(h0)),
                                  __float2bfloat16(v.y - __bfloat162float(h1)));
    L[2 * i + 1] = __nv_bfloat162(__float2bfloat16(v.z - __bfloat162float(h2)),
                                  __float2bfloat16(v.w - __bfloat162float(h3)));
}

// --------- fused weight splits ------------------------------------------------
__global__ void __launch_bounds__(256) split_weights(
    const float* __restrict__ Wqkv, const float* __restrict__ Wo,
    const float* __restrict__ W1,   const float* __restrict__ W2,
    __nv_bfloat16* __restrict__ qkv_h, __nv_bfloat16* __restrict__ qkv_l,
    __nv_bfloat16* __restrict__ wo_h,  __nv_bfloat16* __restrict__ wo_l,
    __nv_bfloat16* __restrict__ w1_h,  __nv_bfloat16* __restrict__ w1_l,
    __nv_bfloat16* __restrict__ w2_h,  __nv_bfloat16* __restrict__ w2_l)
{
    int bid = blockIdx.x;
    const float* W; __nv_bfloat16 *hi, *lo; int K, N, nbx, local;
    if (bid < 3072)      { W = Wqkv; hi = qkv_h; lo = qkv_l; K = DD; N = 3 * DD; nbx = 96;  local = bid; }
    else if (bid < 4096) { W = Wo;   hi = wo_h;  lo = wo_l;  K = DD; N = DD;     nbx = 32;  local = bid - 3072; }
    else if (bid < 8192) { W = W1;   hi = w1_h;  lo = w1_l;  K = DD; N = FF;     nbx = 128; local = bid - 4096; }
    else                 { W = W2;   hi = w2_h;  lo = w2_l;  K = FF; N = DD;     nbx = 32;  local = bid - 8192; }
    int n0 = (local % nbx) * 32, k0 = (local / nbx) * 32;

    __shared__ float t[32][33];
    int tx = threadIdx.x & 31, ty = threadIdx.x >> 5;
#pragma unroll
    for (int dy = 0; dy < 32; dy += 8)
        t[ty + dy][tx] = W[(size_t)(k0 + ty + dy) * N + n0 + tx];
    __syncthreads();
#pragma unroll
    for (int dy = 0; dy < 32; dy += 8) {
        int n = n0 + ty + dy, k = k0 + tx;
        float v = t[tx][ty + dy];
        __nv_bfloat16 h = __float2bfloat16(v);
        hi[(size_t)n * K + k] = h;
        lo[(size_t)n * K + k] = __float2bfloat16(v - __bfloat162float(h));
    }
}

// ------------- split qkv -> Q(hi), K(hi) arrays [bh][s][hd] -------------------
__global__ void __launch_bounds__(256) split_qk(
    const float* __restrict__ qkv,
    __nv_bfloat16* __restrict__ Qh, __nv_bfloat16* __restrict__ Kh)
{
    int part = blockIdx.y;
    long long i = (long long)blockIdx.x * 256 + threadIdx.x;
    long long r = i >> 5;
    int hd = (int)(i & 31) * 4;
    int bh = (int)(r / SS);
    int s_ = (int)(r % SS);
    int b = bh >> 3, h = bh & 7;
    const float* src = qkv + ((size_t)(b * SS + s_)) * 3072 + h * 384 + part * 128 + hd;
    float4 v = *(const float4*)src;
    __nv_bfloat162 hv0(__float2bfloat16(v.x), __float2bfloat16(v.y));
    __nv_bfloat162 hv1(__float2bfloat16(v.z), __float2bfloat16(v.w));
    __nv_bfloat16* H = part ? Kh : Qh;
    size_t o = ((size_t)bh * SS + s_) * HD + hd;
    *(__nv_bfloat162*)(H + o)     = hv0;
    *(__nv_bfloat162*)(H + o + 2) = hv1;
}

// ------------- split + transpose V -> VT [bh][hd][s] (hi only) ----------------
__global__ void __launch_bounds__(256) splitTv(
    const float* __restrict__ qkv,
    __nv_bfloat16* __restrict__ VTh)
{
    __shared__ float t[32][33];
    int s0 = blockIdx.x * 32, hd0 = blockIdx.y * 32;
    int bh = blockIdx.z;
    int b = bh >> 3, h = bh & 7;
    int tx = threadIdx.x & 31, ty = threadIdx.x >> 5;
#pragma unroll
    for (int dy = 0; dy < 32; dy += 8)
        t[ty + dy][tx] = qkv[((size_t)(b * SS + s0 + ty + dy)) * 3072 + h * 384 + 256 + hd0 + tx];
    __syncthreads();
#pragma unroll
    for (int dy = 0; dy < 32; dy += 8) {
        int hd = hd0 + ty + dy, s_ = s0 + tx;
        float v = t[tx][ty + dy];
        size_t o = ((size_t)bh * HD + hd) * SS + s_;
        VTh[o] = __float2bfloat16(v);
    }
}

// ------------- fused residual add + LayerNorm (+ optional split) --------------
__global__ void __launch_bounds__(256) add_ln(
    const float* __restrict__ X, const float* __restrict__ R, float* __restrict__ O,
    __nv_bfloat16* __restrict__ Ohi, __nv_bfloat16* __restrict__ Olo)
{
    long long row = blockIdx.x;
    const float* x = X + row * DD;
    const float* r = R + row * DD;
    int tid = threadIdx.x;

    __shared__ float rs[256], rss[256];

    float v[4];
    float s = 0.f, ss2 = 0.f;
#pragma unroll
    for (int i = 0; i < 4; i++) {
        float y = x[tid + i * 256] + r[tid + i * 256];
        v[i] = y;
        s += y;
        ss2 += y * y;
    }
    rs[tid] = s; rss[tid] = ss2;
    __syncthreads();
    for (int st = 128; st > 0; st >>= 1) {
        if (tid < st) { rs[tid] += rs[tid + st]; rss[tid] += rss[tid + st]; }
        __syncthreads();
    }
    float mean = rs[0] * (1.0f / DD);
    float var  = rss[0] * (1.0f / DD) - mean * mean;
    float inv  = rsqrtf(var + EPS);
#pragma unroll
    for (int i = 0; i < 4; i++) {
        float y = (v[i] - mean) * inv;
        O[row * DD + tid + i * 256] = y;
        if (Ohi) {
            __nv_bfloat16 hb = __float2bfloat16(y);
            Ohi[row * DD + tid + i * 256] = hb;
            Olo[row * DD + tid + i * 256] = __float2bfloat16(y - __bfloat162float(hb));
        }
    }
}

// ------------------------------- launcher -------------------------------------
extern "C" void kernel_launch(void* const* d_in, const int* in_sizes, int n_in,
                              void* d_out, int out_size)
{
    const float* x    = (const float*)d_in[0];
    const float* Wqkv = (const float*)d_in[1];
    const float* Wo   = (const float*)d_in[2];
    const float* W1   = (const float*)d_in[3];
    const float* W2   = (const float*)d_in[4];
    float* out = (float*)d_out;

    float *qkv, *attn, *x1, *ffo;
    cudaGetSymbolAddress((void**)&qkv,  g_qkv);
    cudaGetSymbolAddress((void**)&attn, g_attn);
    cudaGetSymbolAddress((void**)&x1,   g_x1);
    cudaGetSymbolAddress((void**)&ffo,  g_ffo);

    __nv_bfloat16 *xs_h, *xs_l, *wqkv_h, *wqkv_l, *wo_h, *wo_l, *w1_h, *w1_l,
                  *w2_h, *w2_l, *qh, *kh, *vth,
                  *vls_h, *x1s_h, *x1s_l, *ffh_h, *ffh_l;
    cudaGetSymbolAddress((void**)&xs_h,   g_xs_h);
    cudaGetSymbolAddress((void**)&xs_l,   g_xs_l);
    cudaGetSymbolAddress((void**)&wqkv_h, g_wqkv_h);
    cudaGetSymbolAddress((void**)&wqkv_l, g_wqkv_l);
    cudaGetSymbolAddress((void**)&wo_h,   g_wo_h);
    cudaGetSymbolAddress((void**)&wo_l,   g_wo_l);
    cudaGetSymbolAddress((void**)&w1_h,   g_w1_h);
    cudaGetSymbolAddress((void**)&w1_l,   g_w1_l);
    cudaGetSymbolAddress((void**)&w2_h,   g_w2_h);
    cudaGetSymbolAddress((void**)&w2_l,   g_w2_l);
    cudaGetSymbolAddress((void**)&qh,     g_qh);
    cudaGetSymbolAddress((void**)&kh,     g_kh);
    cudaGetSymbolAddress((void**)&vth,    g_vth);
    cudaGetSymbolAddress((void**)&vls_h,  g_vls_h);
    cudaGetSymbolAddress((void**)&x1s_h,  g_x1s_h);
    cudaGetSymbolAddress((void**)&x1s_l,  g_x1s_l);
    cudaGetSymbolAddress((void**)&ffh_h,  g_ffh_h);
    cudaGetSymbolAddress((void**)&ffh_l,  g_ffh_l);

    cudaFuncSetAttribute(tgemm<0>, cudaFuncAttributeMaxDynamicSharedMemorySize, SM_MMA_TOTAL);
    cudaFuncSetAttribute(tgemm<1>, cudaFuncAttributeMaxDynamicSharedMemorySize, SM_MMA_TOTAL);
    cudaFuncSetAttribute(fattn, cudaFuncAttributeMaxDynamicSharedMemorySize, SM_FLASH);

    split_weights<<<12288, 256>>>(Wqkv, Wo, W1, W2,
        wqkv_h, wqkv_l, wo_h, wo_l, w1_h, w1_l, w2_h, w2_l);
    split_flat<<<(long long)ROWS * DD / 1024, 256>>>(x, xs_h, xs_l, (long long)ROWS * DD / 4);

    // 1) QKV = x @ Wqkv (bf16x2)
    tgemm<0><<<dim3(3 * DD / 128, ROWS / 128), 256, SM_MMA_TOTAL>>>(
        xs_h, xs_l, wqkv_h, wqkv_l, qkv, nullptr, nullptr, DD, DD, DD, 3 * DD, 0);

    // 2) split qkv into attention operands (Q hi, K hi, VT hi)
    split_qk<<<dim3((unsigned)((long long)BB * HH * SS * HD / 4 / 256), 2), 256>>>(
        qkv, qh, kh);
    splitTv<<<dim3(SS / 32, HD / 32, BB * HH), 256>>>(qkv, vth);

    // 3) flash attention (pure bf16) -> vals hi
    fattn<<<dim3(SS / 128, BB * HH), 256, SM_FLASH>>>(qh, kh, vth, vls_h);

    // 4) attn = vals @ Wo (bf16x2)
    tgemm<0><<<dim3(DD / 128, ROWS / 128), 256, SM_MMA_TOTAL>>>(
        vls_h, vls_h, wo_h, wo_l, attn, nullptr, nullptr, DD, DD, DD, DD, 0);

    // 5) x1 = LN(x + attn), fused split
    add_ln<<<ROWS, 256>>>(x, attn, x1, x1s_h, x1s_l);

    // 6) ffh = relu(x1 @ W1), hi/lo out (full bf16x3)
    tgemm<1><<<dim3(FF / 128, ROWS / 128), 256, SM_MMA_TOTAL>>>(
        x1s_h, x1s_l, w1_h, w1_l, nullptr, ffh_h, ffh_l, DD, DD, DD, FF, 1);

    // 7) ffo = ffh @ W2 (full bf16x3)
    tgemm<1><<<dim3(DD / 128, ROWS / 128), 256, SM_MMA_TOTAL>>>(
        ffh_h, ffh_l, w2_h, w2_l, ffo, nullptr, nullptr, FF, FF, FF, DD, 0);

    // 8) out = LN(x1 + ffo)
    add_ln<<<ROWS, 256>>>(x1, ffo, out, nullptr, nullptr);
}